// round 4
// baseline (speedup 1.0000x reference)
#include <cuda_runtime.h>
#include <cuda_bf16.h>
#include <cstdint>

#define N_ENT   100000
#define D       128
#define NB_SCAN 49

// ---------------- scratch (static, no allocs) ----------------
__device__ float4  g_neigh4[(size_t)N_ENT * 32];
__device__ uint8_t g_Wbf[4 * 32768];   // bf16 slabs: 0 Ws_hi, 1 Wn_hi, 2 Ws_lo, 3 Wn_lo
__device__ int     g_cnt[N_ENT];
__device__ int     g_start[N_ENT + 1];
__device__ int     g_head[N_ENT];
__device__ int     g_bsum[64];
__device__ int     g_boff[64];
__device__ float2  g_edge[1600000];

// Swizzled offset for word (r, kw) in a [128 rows][64 words] bf16 tile:
// 256B rows; 16B slot index XORed with (r&7) -> conflict-free ldmatrix.
__device__ __forceinline__ uint32_t swz(int r, int kw) {
    return (uint32_t)(r * 256 + ((((kw >> 2) ^ (r & 7))) << 4) + ((kw & 3) << 2));
}

__device__ __forceinline__ uint32_t smem_u32(const void* p) {
    uint32_t a;
    asm("{ .reg .u64 t; cvta.to.shared.u64 t, %1; cvt.u32.u64 %0, t; }" : "=r"(a) : "l"(p));
    return a;
}
__device__ __forceinline__ void ldm_x4(uint32_t* r, uint32_t addr) {
    asm volatile("ldmatrix.sync.aligned.m8n8.x4.shared.b16 {%0,%1,%2,%3}, [%4];"
                 : "=r"(r[0]), "=r"(r[1]), "=r"(r[2]), "=r"(r[3]) : "r"(addr));
}
__device__ __forceinline__ void mma16816(float* c, const uint32_t* a, uint32_t b0, uint32_t b1) {
    asm volatile("mma.sync.aligned.m16n8k16.row.col.f32.bf16.bf16.f32 "
                 "{%0,%1,%2,%3}, {%4,%5,%6,%7}, {%8,%9}, {%0,%1,%2,%3};"
                 : "+f"(c[0]), "+f"(c[1]), "+f"(c[2]), "+f"(c[3])
                 : "r"(a[0]), "r"(a[1]), "r"(a[2]), "r"(a[3]), "r"(b0), "r"(b1));
}

// ---------------- CSR build ----------------
__global__ void k_zero_cnt(int n) {
    int i = blockIdx.x * blockDim.x + threadIdx.x;
    if (i < n) g_cnt[i] = 0;
}
__global__ void k_hist(const int* __restrict__ rows, int E) {
    int i = blockIdx.x * blockDim.x + threadIdx.x;
    if (i < E) atomicAdd(&g_cnt[rows[i]], 1);
}
__global__ void k_scan1(int n) {
    __shared__ int ss[256];
    int b = blockIdx.x, t = threadIdx.x;
    int base = b * 2048 + t * 8;
    int loc[8], s = 0;
#pragma unroll
    for (int i = 0; i < 8; i++) {
        int idx = base + i;
        loc[i] = (idx < n) ? g_cnt[idx] : 0;
        s += loc[i];
    }
    ss[t] = s;
    __syncthreads();
    for (int off = 1; off < 256; off <<= 1) {
        int v = 0;
        if (t >= off) v = ss[t - off];
        __syncthreads();
        if (t >= off) ss[t] += v;
        __syncthreads();
    }
    int excl = ss[t] - s;
#pragma unroll
    for (int i = 0; i < 8; i++) {
        int idx = base + i;
        if (idx < n) g_start[idx] = excl;
        excl += loc[i];
    }
    if (t == 255) g_bsum[b] = ss[255];
}
__global__ void k_scan2(int nb) {
    if (threadIdx.x == 0) {
        int s = 0;
        for (int i = 0; i < nb; i++) { g_boff[i] = s; s += g_bsum[i]; }
    }
}
__global__ void k_scan3(int n, int E) {
    int i = blockIdx.x * blockDim.x + threadIdx.x;
    if (i < n) {
        int v = g_start[i] + g_boff[i >> 11];
        g_start[i] = v;
        g_head[i] = v;
    }
    if (i == 0) g_start[n] = E;
}
__global__ void k_scatter(const int* __restrict__ rows, const int* __restrict__ cols,
                          const float* __restrict__ vals, int E) {
    int i = blockIdx.x * blockDim.x + threadIdx.x;
    if (i < E) {
        int pos = atomicAdd(&g_head[rows[i]], 1);
        g_edge[pos] = make_float2(__int_as_float(cols[i]), vals[i]);
    }
}
__global__ void k_spmm(const float4* __restrict__ embs, int n) {
    int w = (int)((blockIdx.x * blockDim.x + threadIdx.x) >> 5);
    int lane = threadIdx.x & 31;
    if (w >= n) return;
    int s = g_start[w], t = g_start[w + 1];
    float4 acc = make_float4(0.f, 0.f, 0.f, 0.f);
    int e = s;
    for (; e + 4 <= t; e += 4) {
        float2 e0 = g_edge[e], e1 = g_edge[e + 1], e2 = g_edge[e + 2], e3 = g_edge[e + 3];
        float4 r0 = embs[(size_t)__float_as_int(e0.x) * 32 + lane];
        float4 r1 = embs[(size_t)__float_as_int(e1.x) * 32 + lane];
        float4 r2 = embs[(size_t)__float_as_int(e2.x) * 32 + lane];
        float4 r3 = embs[(size_t)__float_as_int(e3.x) * 32 + lane];
        acc.x += e0.y * r0.x + e1.y * r1.x + e2.y * r2.x + e3.y * r3.x;
        acc.y += e0.y * r0.y + e1.y * r1.y + e2.y * r2.y + e3.y * r3.y;
        acc.z += e0.y * r0.z + e1.y * r1.z + e2.y * r2.z + e3.y * r3.z;
        acc.w += e0.y * r0.w + e1.y * r1.w + e2.y * r2.w + e3.y * r3.w;
    }
    for (; e < t; e++) {
        float2 ed = g_edge[e];
        float4 r = embs[(size_t)__float_as_int(ed.x) * 32 + lane];
        acc.x += ed.y * r.x; acc.y += ed.y * r.y;
        acc.z += ed.y * r.z; acc.w += ed.y * r.w;
    }
    g_neigh4[(size_t)w * 32 + lane] = acc;
}

// ---------------- weight prep: bf16 hi/lo slabs, swizzled ----------------
__global__ void k_prep_w(const float* __restrict__ Ws, const float* __restrict__ Wn) {
    int idx = blockIdx.x * blockDim.x + threadIdx.x;   // 4*8192 words
    if (idx >= 4 * 8192) return;
    int slab = idx >> 13, w = idx & 8191;
    int o = w >> 6, kw = w & 63, k = kw * 2;
    const float* W = (slab & 1) ? Wn : Ws;
    float f0 = W[o * 128 + k], f1 = W[o * 128 + k + 1];
    __nv_bfloat16 h0 = __float2bfloat16(f0), h1 = __float2bfloat16(f1);
    __nv_bfloat16 b0, b1;
    if (slab < 2) { b0 = h0; b1 = h1; }
    else {
        b0 = __float2bfloat16(f0 - __bfloat162float(h0));
        b1 = __float2bfloat16(f1 - __bfloat162float(h1));
    }
    uint32_t word = (uint32_t)*(uint16_t*)&b0 | ((uint32_t)*(uint16_t*)&b1 << 16);
    *(uint32_t*)(g_Wbf + slab * 32768 + swz(o, kw)) = word;
}

// ---------------- mma.sync GEMM ----------------
#define SM_BIAS 0
#define SM_W    1024
#define SM_AH   (1024 + 131072)
#define SM_AL   (SM_AH + 32768)
#define SM_DYN  (SM_AL + 32768)

// One K=128 pass: acc += A(swizzled @a_base) * W^T(swizzled @w_base)
__device__ __forceinline__ void gemm_pass(uint32_t a_base, uint32_t w_base,
                                          int warp_m, int warp_n, int lane,
                                          float acc[2][8][4]) {
    int roffA = lane & 15;
    int cselA = lane >> 4;
    int noffB = (lane & 7) + ((lane >> 4) << 3);
    int cselB = (lane >> 3) & 1;
#pragma unroll
    for (int ks = 0; ks < 8; ks++) {
        uint32_t a[2][4];
#pragma unroll
        for (int mi = 0; mi < 2; mi++) {
            int row = warp_m * 32 + mi * 16 + roffA;
            int c = ks * 2 + cselA;
            ldm_x4(a[mi], a_base + (uint32_t)(row * 256 + ((c ^ (row & 7)) << 4)));
        }
#pragma unroll
        for (int np = 0; np < 4; np++) {
            uint32_t b[4];
            int row = warp_n * 64 + np * 16 + noffB;
            int c = ks * 2 + cselB;
            ldm_x4(b, w_base + (uint32_t)(row * 256 + ((c ^ (row & 7)) << 4)));
            mma16816(acc[0][np * 2],     a[0], b[0], b[1]);
            mma16816(acc[0][np * 2 + 1], a[0], b[2], b[3]);
            mma16816(acc[1][np * 2],     a[1], b[0], b[1]);
            mma16816(acc[1][np * 2 + 1], a[1], b[2], b[3]);
        }
    }
}

__global__ __launch_bounds__(256, 1)
void k_mma_gemm(const float* __restrict__ x,
                const float* __restrict__ bs,
                const float* __restrict__ bn,
                float* __restrict__ out, int N) {
    extern __shared__ char sm[];
    uint32_t smb = smem_u32(sm);
    const float* neigh = (const float*)g_neigh4;
    int tid = threadIdx.x, wid = tid >> 5, lane = tid & 31;
    int warp_m = wid >> 1, warp_n = wid & 1;

    if (tid < 128) ((float*)(sm + SM_BIAS))[tid] = bs[tid] + bn[tid];
    {   // weights: straight 128KB copy (pre-swizzled)
        const uint4* src = (const uint4*)g_Wbf;
        uint4* dst = (uint4*)(sm + SM_W);
#pragma unroll
        for (int i = 0; i < 32; i++) dst[tid + i * 256] = src[tid + i * 256];
    }
    __syncthreads();

    uint32_t ah = smb + SM_AH, al = smb + SM_AL;
    uint32_t ws_hi = smb + SM_W, wn_hi = ws_hi + 32768;
    uint32_t ws_lo = ws_hi + 65536, wn_lo = ws_hi + 98304;

    int ntiles = (N + 127) / 128;
    for (int tile = blockIdx.x; tile < ntiles; tile += gridDim.x) {
        int row0 = tile * 128;
        float acc[2][8][4];
#pragma unroll
        for (int mi = 0; mi < 2; mi++)
#pragma unroll
            for (int ni = 0; ni < 8; ni++)
#pragma unroll
                for (int q = 0; q < 4; q++) acc[mi][ni][q] = 0.f;

#pragma unroll
        for (int mat = 0; mat < 2; mat++) {
            const float* src = mat ? neigh : x;
            uint32_t whi = mat ? wn_hi : ws_hi;
            uint32_t wlo = mat ? wn_lo : ws_lo;
            // convert 128x128 fp32 -> A_hi/A_lo bf16 (swizzled)
#pragma unroll 4
            for (int i = 0; i < 32; i++) {
                int idx = i * 256 + tid, r = idx >> 6, kw = idx & 63;
                int gr = row0 + r;
                float2 v = make_float2(0.f, 0.f);
                if (gr < N) v = *(const float2*)(src + (size_t)gr * 128 + kw * 2);
                __nv_bfloat16 h0 = __float2bfloat16(v.x), h1 = __float2bfloat16(v.y);
                __nv_bfloat16 l0 = __float2bfloat16(v.x - __bfloat162float(h0));
                __nv_bfloat16 l1 = __float2bfloat16(v.y - __bfloat162float(h1));
                uint32_t o = swz(r, kw);
                *(uint32_t*)(sm + SM_AH + o) =
                    (uint32_t)*(uint16_t*)&h0 | ((uint32_t)*(uint16_t*)&h1 << 16);
                *(uint32_t*)(sm + SM_AL + o) =
                    (uint32_t)*(uint16_t*)&l0 | ((uint32_t)*(uint16_t*)&l1 << 16);
            }
            __syncthreads();
            gemm_pass(ah, whi, warp_m, warp_n, lane, acc);   // hi * W_hi
            gemm_pass(ah, wlo, warp_m, warp_n, lane, acc);   // hi * W_lo
            gemm_pass(al, whi, warp_m, warp_n, lane, acc);   // lo * W_hi
            __syncthreads();   // all warps done reading A before refill/next tile
        }

        // epilogue: bias + leaky + store from C-frags
        {
            const float* sb = (const float*)(sm + SM_BIAS);
            int r_base = row0 + warp_m * 32 + (lane >> 2);
            int cq = (lane & 3) * 2;
#pragma unroll
            for (int mi = 0; mi < 2; mi++) {
                int gr0 = r_base + mi * 16;
#pragma unroll
                for (int ni = 0; ni < 8; ni++) {
                    int col = warp_n * 64 + ni * 8 + cq;
                    float b0 = sb[col], b1 = sb[col + 1];
                    if (gr0 < N) {
                        float v0 = acc[mi][ni][0] + b0, v1 = acc[mi][ni][1] + b1;
                        v0 = v0 > 0.f ? v0 : 0.01f * v0;
                        v1 = v1 > 0.f ? v1 : 0.01f * v1;
                        *(float2*)(out + (size_t)gr0 * 128 + col) = make_float2(v0, v1);
                    }
                    if (gr0 + 8 < N) {
                        float v2 = acc[mi][ni][2] + b0, v3 = acc[mi][ni][3] + b1;
                        v2 = v2 > 0.f ? v2 : 0.01f * v2;
                        v3 = v3 > 0.f ? v3 : 0.01f * v3;
                        *(float2*)(out + (size_t)(gr0 + 8) * 128 + col) = make_float2(v2, v3);
                    }
                }
            }
        }
    }
}

extern "C" void kernel_launch(void* const* d_in, const int* in_sizes, int n_in,
                              void* d_out, int out_size) {
    const float* embs = (const float*)d_in[0];
    const int*   rows = (const int*)d_in[1];
    const int*   cols = (const int*)d_in[2];
    const float* vals = (const float*)d_in[3];
    const float* Ws   = (const float*)d_in[4];
    const float* bs   = (const float*)d_in[5];
    const float* Wn   = (const float*)d_in[6];
    const float* bn   = (const float*)d_in[7];
    float* out = (float*)d_out;

    int N = in_sizes[0] / D;
    int E = in_sizes[1];

    cudaFuncSetAttribute(k_mma_gemm, cudaFuncAttributeMaxDynamicSharedMemorySize, SM_DYN);

    k_prep_w<<<(4 * 8192 + 255) / 256, 256>>>(Ws, Wn);
    k_zero_cnt<<<(N + 255) / 256, 256>>>(N);
    k_hist<<<(E + 255) / 256, 256>>>(rows, E);
    k_scan1<<<NB_SCAN, 256>>>(N);
    k_scan2<<<1, 32>>>(NB_SCAN);
    k_scan3<<<(N + 255) / 256, 256>>>(N, E);
    k_scatter<<<(E + 255) / 256, 256>>>(rows, cols, vals, E);
    k_spmm<<<(N + 7) / 8, 256>>>((const float4*)embs, N);
    k_mma_gemm<<<148, 256, SM_DYN>>>(embs, bs, bn, out, N);
}